// round 16
// baseline (speedup 1.0000x reference)
#include <cuda_runtime.h>
#include <cuda_fp16.h>
#include <cuda_bf16.h>
#include <cstdint>

// ForwardWarp, N=4, C=3, H=1080, W=1920, fp32 in/out.
// r15 components (parity-split f16x4 scratch, 16B v4.f16x2 RED per tap-pair,
// 2px/thread finalize, priority streams) + group-of-2 scatter staggering:
//   zero{0,1} -> scatter{0,1} (concurrent) -> scatter{2,3} (concurrent)
//   finalize{0,1} run under scatter{2,3}; only finalize{2,3} exposed.

#define FW_N 4
#define FW_C 3
#define FW_H 1080
#define FW_W 1920
#define FW_HW (FW_H * FW_W)
#define FW_PIX (FW_N * FW_HW)
#define FW_ODD_STRIDE (FW_HW + 2)          // per-batch odd-slice stride (even)

// 8 bytes per pixel: {f16x2(c0,c1), f16x2(c2,0)}
__device__ __align__(128) uint2 fw_even[FW_PIX];                  // 66.4 MB
__device__ __align__(128) uint2 fw_odd[FW_N * FW_ODD_STRIDE];     // 66.4 MB
// both zero-initialized at module load

// ---------------- zero: two batches per launch ----------------
#define ZERO_BLOCKS 2368
#define ZERO_THREADS 256
__global__ __launch_bounds__(ZERO_THREADS) void fw_zero2_kernel(int n0)
{
    const uint4 z = make_uint4(0u, 0u, 0u, 0u);
    const int stride = ZERO_BLOCKS * ZERO_THREADS;
    const int t0 = blockIdx.x * ZERO_THREADS + threadIdx.x;

    uint4* se = reinterpret_cast<uint4*>(fw_even + (size_t)n0 * FW_HW);
    for (int i = t0; i < FW_HW; i += stride) se[i] = z;          // 2 batches = FW_HW uint4s

    uint4* so = reinterpret_cast<uint4*>(fw_odd + (size_t)n0 * FW_ODD_STRIDE);
    for (int i = t0; i < FW_ODD_STRIDE; i += stride) so[i] = z;  // 2 batches
}

// ---------------- scatter ----------------
__device__ __forceinline__ uint32_t h2u(float a, float b)
{
    __half2 h = __floats2half2_rn(a, b);
    return *reinterpret_cast<const uint32_t*>(&h);
}

__device__ __forceinline__ void red_add_v2h2(uint2* p, uint32_t h01, uint32_t h23)
{
    asm volatile("red.global.add.noftz.v2.f16x2 [%0], {%1, %2};"
                 :: "l"(p), "r"(h01), "r"(h23) : "memory");
}

__device__ __forceinline__ void red_add_v4h2(uint2* p, uint32_t a, uint32_t b,
                                             uint32_t c, uint32_t d)
{
    asm volatile("red.global.add.noftz.v4.f16x2 [%0], {%1, %2, %3, %4};"
                 :: "l"(p), "r"(a), "r"(b), "r"(c), "r"(d) : "memory");
}

// Grid: (FW_W/128, FW_H, 1), block 128; batch passed as arg.
__global__ __launch_bounds__(128) void fw_scatter_kernel(
    const float* __restrict__ img,
    const float* __restrict__ flo,
    int n)
{
    const int w = blockIdx.x * 128 + threadIdx.x;
    const int h = blockIdx.y;
    const int hw = h * FW_W + w;

    // flo channel 0 -> column shift, channel 1 -> row shift.
    const float* flo_n = flo + (size_t)n * 2 * FW_HW;
    const float ycol = __ldcs(flo_n + hw);
    const float xrow = __ldcs(flo_n + FW_HW + hw);

    const float xf = floorf(xrow);
    const float yf = floorf(ycol);
    const int ix = (int)xf;
    const int iy = (int)yf;
    const float fx = xrow - xf;   // row frac
    const float fy = ycol - yf;   // col frac

    const float* img_n = img + (size_t)n * FW_C * FW_HW;
    const float c0 = __ldcs(img_n + hw);
    const float c1 = __ldcs(img_n + FW_HW + hw);
    const float c2 = __ldcs(img_n + 2 * FW_HW + hw);

    const float wx0 = 1.0f - fx;
    const float wy0 = 1.0f - fy;

    const int rbase = h + ix;
    const int cc = w + iy;
    const int par = cc & 1;

    uint2* __restrict__ ev_n = fw_even + (size_t)n * FW_HW;
    uint2* __restrict__ od_n = fw_odd + (size_t)n * FW_ODD_STRIDE;

    #pragma unroll
    for (int dx = 0; dx < 2; dx++) {
        const int rr = rbase + dx;
        if ((unsigned)rr >= (unsigned)FW_H) continue;
        const float wx = dx ? fx : wx0;
        const float w0 = wx * wy0;   // column cc
        const float w1 = wx * fy;    // column cc + 1
        const int rowoff = rr * FW_W;

        if ((unsigned)cc <= (unsigned)(FW_W - 2)) {
            uint2* p = par ? (od_n + rowoff + cc + 1) : (ev_n + rowoff + cc);
            red_add_v4h2(p,
                         h2u(c0 * w0, c1 * w0), h2u(c2 * w0, 0.0f),
                         h2u(c0 * w1, c1 * w1), h2u(c2 * w1, 0.0f));
        } else {
            if ((unsigned)cc < (unsigned)FW_W)
                red_add_v2h2(ev_n + rowoff + cc, h2u(c0 * w0, c1 * w0), h2u(c2 * w0, 0.0f));
            if ((unsigned)(cc + 1) < (unsigned)FW_W)
                red_add_v2h2(ev_n + rowoff + cc + 1, h2u(c0 * w1, c1 * w1), h2u(c2 * w1, 0.0f));
        }
    }
}

// ---------------- finalize: 2 px/thread, sum parity buffers -> fp32 NCHW ----------------
// Grid: (6, FW_H, 1), block 160  (6*160 = 960 = W/2 pixel-pairs per row).
__global__ __launch_bounds__(160) void fw_finalize_kernel(float* __restrict__ out, int n)
{
    const int t = blockIdx.x * 160 + threadIdx.x;   // pixel-pair index in row
    const int h = blockIdx.y;
    const int hw = h * FW_W + 2 * t;                // even pixel index

    const uint4* ep = reinterpret_cast<const uint4*>(fw_even + (size_t)n * FW_HW + hw);
    uint4 ev;
    asm volatile("ld.global.cs.v4.u32 {%0, %1, %2, %3}, [%4];"
                 : "=r"(ev.x), "=r"(ev.y), "=r"(ev.z), "=r"(ev.w) : "l"(ep));

    const uint2* op = fw_odd + ((size_t)n * FW_ODD_STRIDE + hw + 1);
    uint32_t oa, ob, oc, od;
    asm volatile("ld.global.cs.v2.u32 {%0, %1}, [%2];" : "=r"(oa), "=r"(ob) : "l"(op));
    asm volatile("ld.global.cs.v2.u32 {%0, %1}, [%2];" : "=r"(oc), "=r"(od) : "l"(op + 1));

    const float2 e0_01 = __half22float2(*reinterpret_cast<const __half2*>(&ev.x));
    const float2 e0_23 = __half22float2(*reinterpret_cast<const __half2*>(&ev.y));
    const float2 e1_01 = __half22float2(*reinterpret_cast<const __half2*>(&ev.z));
    const float2 e1_23 = __half22float2(*reinterpret_cast<const __half2*>(&ev.w));
    const float2 o0_01 = __half22float2(*reinterpret_cast<const __half2*>(&oa));
    const float2 o0_23 = __half22float2(*reinterpret_cast<const __half2*>(&ob));
    const float2 o1_01 = __half22float2(*reinterpret_cast<const __half2*>(&oc));
    const float2 o1_23 = __half22float2(*reinterpret_cast<const __half2*>(&od));

    float* __restrict__ out_n = out + (size_t)n * FW_C * FW_HW;
    const float a0 = e0_01.x + o0_01.x, b0 = e1_01.x + o1_01.x;   // c0: px0, px1
    const float a1 = e0_01.y + o0_01.y, b1 = e1_01.y + o1_01.y;   // c1
    const float a2 = e0_23.x + o0_23.x, b2 = e1_23.x + o1_23.x;   // c2

    asm volatile("st.global.cs.v2.f32 [%0], {%1, %2};"
                 :: "l"(out_n + hw),             "f"(a0), "f"(b0) : "memory");
    asm volatile("st.global.cs.v2.f32 [%0], {%1, %2};"
                 :: "l"(out_n + FW_HW + hw),     "f"(a1), "f"(b1) : "memory");
    asm volatile("st.global.cs.v2.f32 [%0], {%1, %2};"
                 :: "l"(out_n + 2 * FW_HW + hw), "f"(a2), "f"(b2) : "memory");
}

// ---------------- streams/events: created once at static init ----------------
struct FwResources {
    cudaStream_t zs;          // zero chain (high prio)
    cudaStream_t cs[FW_N];    // per-batch scatter chains (high prio)
    cudaStream_t fs;          // finalize stream (low prio)
    cudaEvent_t  root;
    cudaEvent_t  ez01, ez23;  // group zeros done
    cudaEvent_t  es[FW_N];    // scatter[n] done
    cudaEvent_t  efin;
    FwResources() {
        int lo = 0, hi = 0;
        cudaDeviceGetStreamPriorityRange(&lo, &hi);
        cudaStreamCreateWithPriority(&zs, cudaStreamNonBlocking, hi);
        cudaStreamCreateWithPriority(&fs, cudaStreamNonBlocking, lo);
        cudaEventCreateWithFlags(&root, cudaEventDisableTiming);
        cudaEventCreateWithFlags(&ez01, cudaEventDisableTiming);
        cudaEventCreateWithFlags(&ez23, cudaEventDisableTiming);
        cudaEventCreateWithFlags(&efin, cudaEventDisableTiming);
        for (int i = 0; i < FW_N; i++) {
            cudaStreamCreateWithPriority(&cs[i], cudaStreamNonBlocking, hi);
            cudaEventCreateWithFlags(&es[i], cudaEventDisableTiming);
        }
    }
};
static FwResources g_fw;

extern "C" void kernel_launch(void* const* d_in, const int* in_sizes, int n_in,
                              void* d_out, int out_size)
{
    const float* img = (const float*)d_in[0];
    const float* flo = (const float*)d_in[1];
    float* out = (float*)d_out;

    cudaEventRecord(g_fw.root, 0);
    cudaStreamWaitEvent(g_fw.zs, g_fw.root, 0);

    // Group zeros: batches {0,1}, then {2,3}.
    fw_zero2_kernel<<<ZERO_BLOCKS, ZERO_THREADS, 0, g_fw.zs>>>(0);
    cudaEventRecord(g_fw.ez01, g_fw.zs);
    fw_zero2_kernel<<<ZERO_BLOCKS, ZERO_THREADS, 0, g_fw.zs>>>(2);
    cudaEventRecord(g_fw.ez23, g_fw.zs);

    dim3 sgrid(FW_W / 128, FW_H, 1);

    // Group A scatters (batches 0,1): concurrent, gated on zero01.
    for (int n = 0; n < 2; n++) {
        cudaStreamWaitEvent(g_fw.cs[n], g_fw.ez01, 0);
        fw_scatter_kernel<<<sgrid, 128, 0, g_fw.cs[n]>>>(img, flo, n);
        cudaEventRecord(g_fw.es[n], g_fw.cs[n]);
    }

    // Group B scatters (batches 2,3): gated on zero23 AND group A completion
    // (stagger so finalizes 0,1 can hide under them).
    for (int n = 2; n < 4; n++) {
        cudaStreamWaitEvent(g_fw.cs[n], g_fw.ez23, 0);
        cudaStreamWaitEvent(g_fw.cs[n], g_fw.es[0], 0);
        cudaStreamWaitEvent(g_fw.cs[n], g_fw.es[1], 0);
        fw_scatter_kernel<<<sgrid, 128, 0, g_fw.cs[n]>>>(img, flo, n);
        cudaEventRecord(g_fw.es[n], g_fw.cs[n]);
    }

    // Finalizes on low-priority stream; 0,1 overlap scatters 2,3.
    dim3 fgrid(6, FW_H, 1);
    for (int n = 0; n < FW_N; n++) {
        cudaStreamWaitEvent(g_fw.fs, g_fw.es[n], 0);
        fw_finalize_kernel<<<fgrid, 160, 0, g_fw.fs>>>(out, n);
    }
    cudaEventRecord(g_fw.efin, g_fw.fs);
    cudaStreamWaitEvent(0, g_fw.efin, 0);
}

// round 17
// speedup vs baseline: 1.2576x; 1.2576x over previous
#include <cuda_runtime.h>
#include <cuda_fp16.h>
#include <cuda_bf16.h>
#include <cstdint>

// ForwardWarp, N=4, C=3, H=1080, W=1920, fp32 in/out.
// r15 topology (best measured): parity-split f16x4 scratch, one 16B
// red.add.noftz.v4.f16x2 per bilinear tap-pair, 4 concurrent per-batch
// scatter chains, finalizes on low-priority streams AFTER scatters.
// This round: even/odd zeros run concurrently on 2 streams (shrinks the
// exposed zero[0] head); finalizes alternate across 2 low-prio streams
// (removes serial launch gaps in the tail).

#define FW_N 4
#define FW_C 3
#define FW_H 1080
#define FW_W 1920
#define FW_HW (FW_H * FW_W)
#define FW_PIX (FW_N * FW_HW)
#define FW_ODD_STRIDE (FW_HW + 2)          // per-batch odd-slice stride (even)

// 8 bytes per pixel: {f16x2(c0,c1), f16x2(c2,0)}
__device__ __align__(128) uint2 fw_even[FW_PIX];                  // 66.4 MB
__device__ __align__(128) uint2 fw_odd[FW_N * FW_ODD_STRIDE];     // 66.4 MB
// both zero-initialized at module load

// ---------------- per-batch zero: even / odd buffers separately ----------------
#define ZERO_BLOCKS 1184
#define ZERO_THREADS 256
__global__ __launch_bounds__(ZERO_THREADS) void fw_zero_even_kernel(int n)
{
    const uint4 z = make_uint4(0u, 0u, 0u, 0u);
    const int stride = ZERO_BLOCKS * ZERO_THREADS;
    uint4* se = reinterpret_cast<uint4*>(fw_even + (size_t)n * FW_HW);
    for (int i = blockIdx.x * ZERO_THREADS + threadIdx.x; i < FW_HW / 2; i += stride)
        se[i] = z;
}

__global__ __launch_bounds__(ZERO_THREADS) void fw_zero_odd_kernel(int n)
{
    const uint4 z = make_uint4(0u, 0u, 0u, 0u);
    const int stride = ZERO_BLOCKS * ZERO_THREADS;
    uint4* so = reinterpret_cast<uint4*>(fw_odd + (size_t)n * FW_ODD_STRIDE);
    for (int i = blockIdx.x * ZERO_THREADS + threadIdx.x; i < FW_ODD_STRIDE / 2; i += stride)
        so[i] = z;
}

// ---------------- scatter ----------------
__device__ __forceinline__ uint32_t h2u(float a, float b)
{
    __half2 h = __floats2half2_rn(a, b);
    return *reinterpret_cast<const uint32_t*>(&h);
}

__device__ __forceinline__ void red_add_v2h2(uint2* p, uint32_t h01, uint32_t h23)
{
    asm volatile("red.global.add.noftz.v2.f16x2 [%0], {%1, %2};"
                 :: "l"(p), "r"(h01), "r"(h23) : "memory");
}

__device__ __forceinline__ void red_add_v4h2(uint2* p, uint32_t a, uint32_t b,
                                             uint32_t c, uint32_t d)
{
    asm volatile("red.global.add.noftz.v4.f16x2 [%0], {%1, %2, %3, %4};"
                 :: "l"(p), "r"(a), "r"(b), "r"(c), "r"(d) : "memory");
}

// Grid: (FW_W/128, FW_H, 1), block 128; batch passed as arg.
__global__ __launch_bounds__(128) void fw_scatter_kernel(
    const float* __restrict__ img,
    const float* __restrict__ flo,
    int n)
{
    const int w = blockIdx.x * 128 + threadIdx.x;
    const int h = blockIdx.y;
    const int hw = h * FW_W + w;

    // flo channel 0 -> column shift, channel 1 -> row shift.
    const float* flo_n = flo + (size_t)n * 2 * FW_HW;
    const float ycol = __ldcs(flo_n + hw);
    const float xrow = __ldcs(flo_n + FW_HW + hw);

    const float xf = floorf(xrow);
    const float yf = floorf(ycol);
    const int ix = (int)xf;
    const int iy = (int)yf;
    const float fx = xrow - xf;   // row frac
    const float fy = ycol - yf;   // col frac

    const float* img_n = img + (size_t)n * FW_C * FW_HW;
    const float c0 = __ldcs(img_n + hw);
    const float c1 = __ldcs(img_n + FW_HW + hw);
    const float c2 = __ldcs(img_n + 2 * FW_HW + hw);

    const float wx0 = 1.0f - fx;
    const float wy0 = 1.0f - fy;

    const int rbase = h + ix;
    const int cc = w + iy;
    const int par = cc & 1;

    uint2* __restrict__ ev_n = fw_even + (size_t)n * FW_HW;
    uint2* __restrict__ od_n = fw_odd + (size_t)n * FW_ODD_STRIDE;

    #pragma unroll
    for (int dx = 0; dx < 2; dx++) {
        const int rr = rbase + dx;
        if ((unsigned)rr >= (unsigned)FW_H) continue;
        const float wx = dx ? fx : wx0;
        const float w0 = wx * wy0;   // column cc
        const float w1 = wx * fy;    // column cc + 1
        const int rowoff = rr * FW_W;

        if ((unsigned)cc <= (unsigned)(FW_W - 2)) {
            uint2* p = par ? (od_n + rowoff + cc + 1) : (ev_n + rowoff + cc);
            red_add_v4h2(p,
                         h2u(c0 * w0, c1 * w0), h2u(c2 * w0, 0.0f),
                         h2u(c0 * w1, c1 * w1), h2u(c2 * w1, 0.0f));
        } else {
            if ((unsigned)cc < (unsigned)FW_W)
                red_add_v2h2(ev_n + rowoff + cc, h2u(c0 * w0, c1 * w0), h2u(c2 * w0, 0.0f));
            if ((unsigned)(cc + 1) < (unsigned)FW_W)
                red_add_v2h2(ev_n + rowoff + cc + 1, h2u(c0 * w1, c1 * w1), h2u(c2 * w1, 0.0f));
        }
    }
}

// ---------------- finalize: 2 px/thread, sum parity buffers -> fp32 NCHW ----------------
// Grid: (6, FW_H, 1), block 160  (6*160 = 960 = W/2 pixel-pairs per row).
__global__ __launch_bounds__(160) void fw_finalize_kernel(float* __restrict__ out, int n)
{
    const int t = blockIdx.x * 160 + threadIdx.x;   // pixel-pair index in row
    const int h = blockIdx.y;
    const int hw = h * FW_W + 2 * t;                // even pixel index

    const uint4* ep = reinterpret_cast<const uint4*>(fw_even + (size_t)n * FW_HW + hw);
    uint4 ev;
    asm volatile("ld.global.cs.v4.u32 {%0, %1, %2, %3}, [%4];"
                 : "=r"(ev.x), "=r"(ev.y), "=r"(ev.z), "=r"(ev.w) : "l"(ep));

    const uint2* op = fw_odd + ((size_t)n * FW_ODD_STRIDE + hw + 1);
    uint32_t oa, ob, oc, od;
    asm volatile("ld.global.cs.v2.u32 {%0, %1}, [%2];" : "=r"(oa), "=r"(ob) : "l"(op));
    asm volatile("ld.global.cs.v2.u32 {%0, %1}, [%2];" : "=r"(oc), "=r"(od) : "l"(op + 1));

    const float2 e0_01 = __half22float2(*reinterpret_cast<const __half2*>(&ev.x));
    const float2 e0_23 = __half22float2(*reinterpret_cast<const __half2*>(&ev.y));
    const float2 e1_01 = __half22float2(*reinterpret_cast<const __half2*>(&ev.z));
    const float2 e1_23 = __half22float2(*reinterpret_cast<const __half2*>(&ev.w));
    const float2 o0_01 = __half22float2(*reinterpret_cast<const __half2*>(&oa));
    const float2 o0_23 = __half22float2(*reinterpret_cast<const __half2*>(&ob));
    const float2 o1_01 = __half22float2(*reinterpret_cast<const __half2*>(&oc));
    const float2 o1_23 = __half22float2(*reinterpret_cast<const __half2*>(&od));

    float* __restrict__ out_n = out + (size_t)n * FW_C * FW_HW;
    const float a0 = e0_01.x + o0_01.x, b0 = e1_01.x + o1_01.x;   // c0: px0, px1
    const float a1 = e0_01.y + o0_01.y, b1 = e1_01.y + o1_01.y;   // c1
    const float a2 = e0_23.x + o0_23.x, b2 = e1_23.x + o1_23.x;   // c2

    asm volatile("st.global.cs.v2.f32 [%0], {%1, %2};"
                 :: "l"(out_n + hw),             "f"(a0), "f"(b0) : "memory");
    asm volatile("st.global.cs.v2.f32 [%0], {%1, %2};"
                 :: "l"(out_n + FW_HW + hw),     "f"(a1), "f"(b1) : "memory");
    asm volatile("st.global.cs.v2.f32 [%0], {%1, %2};"
                 :: "l"(out_n + 2 * FW_HW + hw), "f"(a2), "f"(b2) : "memory");
}

// ---------------- streams/events: created once at static init ----------------
struct FwResources {
    cudaStream_t zse, zso;    // zero chains: even / odd buffers (high prio)
    cudaStream_t cs[FW_N];    // per-batch scatter chains (high prio)
    cudaStream_t fs[2];       // finalize streams (low prio)
    cudaEvent_t  root;
    cudaEvent_t  eze[FW_N];   // even-zero[n] done
    cudaEvent_t  ezo[FW_N];   // odd-zero[n] done
    cudaEvent_t  es[FW_N];    // scatter[n] done
    cudaEvent_t  ef[2];
    FwResources() {
        int lo = 0, hi = 0;
        cudaDeviceGetStreamPriorityRange(&lo, &hi);
        cudaStreamCreateWithPriority(&zse, cudaStreamNonBlocking, hi);
        cudaStreamCreateWithPriority(&zso, cudaStreamNonBlocking, hi);
        cudaStreamCreateWithPriority(&fs[0], cudaStreamNonBlocking, lo);
        cudaStreamCreateWithPriority(&fs[1], cudaStreamNonBlocking, lo);
        cudaEventCreateWithFlags(&root, cudaEventDisableTiming);
        cudaEventCreateWithFlags(&ef[0], cudaEventDisableTiming);
        cudaEventCreateWithFlags(&ef[1], cudaEventDisableTiming);
        for (int i = 0; i < FW_N; i++) {
            cudaStreamCreateWithPriority(&cs[i], cudaStreamNonBlocking, hi);
            cudaEventCreateWithFlags(&eze[i], cudaEventDisableTiming);
            cudaEventCreateWithFlags(&ezo[i], cudaEventDisableTiming);
            cudaEventCreateWithFlags(&es[i], cudaEventDisableTiming);
        }
    }
};
static FwResources g_fw;

extern "C" void kernel_launch(void* const* d_in, const int* in_sizes, int n_in,
                              void* d_out, int out_size)
{
    const float* img = (const float*)d_in[0];
    const float* flo = (const float*)d_in[1];
    float* out = (float*)d_out;

    cudaEventRecord(g_fw.root, 0);
    cudaStreamWaitEvent(g_fw.zse, g_fw.root, 0);
    cudaStreamWaitEvent(g_fw.zso, g_fw.root, 0);

    // Even/odd zeros in parallel on two streams; per-batch events gate scatters.
    for (int n = 0; n < FW_N; n++) {
        fw_zero_even_kernel<<<ZERO_BLOCKS, ZERO_THREADS, 0, g_fw.zse>>>(n);
        cudaEventRecord(g_fw.eze[n], g_fw.zse);
        fw_zero_odd_kernel<<<ZERO_BLOCKS, ZERO_THREADS, 0, g_fw.zso>>>(n);
        cudaEventRecord(g_fw.ezo[n], g_fw.zso);
    }

    dim3 sgrid(FW_W / 128, FW_H, 1);
    for (int n = 0; n < FW_N; n++) {
        cudaStreamWaitEvent(g_fw.cs[n], g_fw.eze[n], 0);
        cudaStreamWaitEvent(g_fw.cs[n], g_fw.ezo[n], 0);
        fw_scatter_kernel<<<sgrid, 128, 0, g_fw.cs[n]>>>(img, flo, n);
        cudaEventRecord(g_fw.es[n], g_fw.cs[n]);
    }

    // Finalizes alternate across two low-prio streams (compress launch gaps).
    dim3 fgrid(6, FW_H, 1);
    for (int n = 0; n < FW_N; n++) {
        cudaStream_t s = g_fw.fs[n & 1];
        cudaStreamWaitEvent(s, g_fw.es[n], 0);
        fw_finalize_kernel<<<fgrid, 160, 0, s>>>(out, n);
    }
    cudaEventRecord(g_fw.ef[0], g_fw.fs[0]);
    cudaEventRecord(g_fw.ef[1], g_fw.fs[1]);
    cudaStreamWaitEvent(0, g_fw.ef[0], 0);
    cudaStreamWaitEvent(0, g_fw.ef[1], 0);
}